// round 4
// baseline (speedup 1.0000x reference)
#include <cuda_runtime.h>
#include <stdint.h>

// Energy4D: 4x multi-resolution hash-grid encodings (instant-NGP style).
// L=16 levels, F=2 feats, HMAP=2^19, BASE=32, GROWTH=2 -> res_l = 32<<l.
// Level sizes: l0 dense 32768, l1 dense 262144, l>=2 hashed 524288 each.
//
// Numerics must match XLA's lowering bit-for-bit because pos = u*(res-1)
// amplifies ulp-level differences in u by up to 2^20.
//  - XLA algebraic simplifier: x / const -> x * rn(1/const)  (NOT a true div)
//  - w = rn(u*resm1) - (float)p0_clipped   (plain sub, no fma)
//  - u = clip((x+1)*0.5)  (/2 is exact as *0.5)
// All math via __f*_rn intrinsics so --use_fast_math can't contract/approx.

constexpr unsigned HMASK = (1u << 19) - 1u;
constexpr unsigned P1 = 2654435761u;
constexpr unsigned P2 = 805459861u;

__device__ __forceinline__ float clip01(float v) {
    return fminf(fmaxf(v, 0.0f), 1.0f);
}

__global__ __launch_bounds__(256) void energy4d_kernel(
    const float4* __restrict__ coords,
    const float4* __restrict__ refc,
    const float2* __restrict__ t0,
    const float2* __restrict__ t1,
    const float2* __restrict__ t2,
    const float2* __restrict__ t3,
    float2* __restrict__ out)   // out viewed as float2: elem = pt*64 + e*16 + l
{
    const int warp = threadIdx.x >> 5;
    const int lane = threadIdx.x & 31;
    const int e    = warp & 3;                               // encoding id
    const int pt   = (blockIdx.x * 2 + (warp >> 2)) * 32 + lane;

    const float4 c = coords[pt];
    const float4 r = refc[pt];

    // Compile-time correctly-rounded reciprocals (== XLA's folded 1/const).
    const float R180   = 1.0f / 180.0f;
    const float R360   = 1.0f / 360.0f;
    const float R20000 = 1.0f / 20000.0f;

    // rel = coords - refc; _norm: clip((v - lo) * rn(1/(hi-lo)))
    float nx = clip01(__fmul_rn(__fadd_rn(__fsub_rn(c.x, r.x), 90.0f),    R180));
    float ny = clip01(__fmul_rn(__fadd_rn(__fsub_rn(c.y, r.y), 180.0f),   R360));
    float nz = clip01(__fmul_rn(__fadd_rn(__fsub_rn(c.z, r.z), 11000.0f), R20000));
    float nt = clip01(__fsub_rn(c.w, r.w));                   // (v-0)/1
    // t_s = (t*2 - 1) * 0.9
    float tsn = __fmul_rn(__fsub_rn(__fmul_rn(nt, 2.0f), 1.0f), 0.9f);

    // hash_encode's u = clip((x + 1)/2, 0, 1); /2 == *0.5 exactly
    float ux = clip01(__fmul_rn(__fadd_rn(nx,  1.0f), 0.5f));
    float uy = clip01(__fmul_rn(__fadd_rn(ny,  1.0f), 0.5f));
    float uz = clip01(__fmul_rn(__fadd_rn(nz,  1.0f), 0.5f));
    float ut = clip01(__fmul_rn(__fadd_rn(tsn, 1.0f), 0.5f));

    // encoding dim selection: e0=(x,y,z) e1=(x,y,t) e2=(y,z,t) e3=(x,z,t)
    const float ua = (e == 2) ? uy : ux;
    const float ub = (e <= 1) ? uy : uz;
    const float uc = (e == 0) ? uz : ut;
    const float2* __restrict__ tbl =
        (e == 0) ? t0 : (e == 1) ? t1 : (e == 2) ? t2 : t3;

    float2* optr = out + (size_t)pt * 64 + (size_t)e * 16;

    int off = 0;
    #pragma unroll
    for (int l = 0; l < 16; ++l) {
        const int   res   = 32 << l;
        const float resm1 = (float)(res - 1);

        float pa = __fmul_rn(ua, resm1);
        float pb = __fmul_rn(ub, resm1);
        float pc = __fmul_rn(uc, resm1);
        int a0 = min(max((int)floorf(pa), 0), res - 2);
        int b0 = min(max((int)floorf(pb), 0), res - 2);
        int c0 = min(max((int)floorf(pc), 0), res - 2);
        // w = rn(product) - clipped p0 (plain sub — matches reference)
        float wa = __fsub_rn(pa, (float)a0);
        float wb = __fsub_rn(pb, (float)b0);
        float wc = __fsub_rn(pc, (float)c0);

        int idx[8];
        if (l >= 2) {
            // hashed: h = a*1 ^ b*P1 ^ c*P2 (uint32 wrap), idx = (h & HMASK) + off
            unsigned ha0 = (unsigned)a0,      ha1 = ha0 + 1u;
            unsigned hb0 = (unsigned)b0 * P1, hb1 = hb0 + P1;
            unsigned hc0 = (unsigned)c0 * P2, hc1 = hc0 + P2;
            idx[0] = (int)((ha0 ^ hb0 ^ hc0) & HMASK) + off;
            idx[1] = (int)((ha1 ^ hb0 ^ hc0) & HMASK) + off;
            idx[2] = (int)((ha0 ^ hb1 ^ hc0) & HMASK) + off;
            idx[3] = (int)((ha1 ^ hb1 ^ hc0) & HMASK) + off;
            idx[4] = (int)((ha0 ^ hb0 ^ hc1) & HMASK) + off;
            idx[5] = (int)((ha1 ^ hb0 ^ hc1) & HMASK) + off;
            idx[6] = (int)((ha0 ^ hb1 ^ hc1) & HMASK) + off;
            idx[7] = (int)((ha1 ^ hb1 ^ hc1) & HMASK) + off;
        } else {
            // dense: idx = a + res*(b + res*c) + off
            const int rr = res * res;
            int base = a0 + res * (b0 + res * c0) + off;
            idx[0] = base;
            idx[1] = base + 1;
            idx[2] = base + res;
            idx[3] = base + res + 1;
            idx[4] = base + rr;
            idx[5] = base + rr + 1;
            idx[6] = base + rr + res;
            idx[7] = base + rr + res + 1;
        }

        // 8 independent gathers (MLP=8 per level)
        float2 f[8];
        #pragma unroll
        for (int i = 0; i < 8; ++i) f[i] = __ldg(&tbl[idx[i]]);

        // corner weights ((d0*d1)*d2) + sequential reduction (i = 0..7)
        const float oma = __fsub_rn(1.0f, wa);
        const float omb = __fsub_rn(1.0f, wb);
        const float omc = __fsub_rn(1.0f, wc);
        float accx = 0.0f, accy = 0.0f;
        #pragma unroll
        for (int i = 0; i < 8; ++i) {
            float cwa = (i & 1) ? wa : oma;
            float cwb = (i & 2) ? wb : omb;
            float cwc = (i & 4) ? wc : omc;
            float cw  = __fmul_rn(__fmul_rn(cwa, cwb), cwc);
            accx = __fadd_rn(accx, __fmul_rn(f[i].x, cw));
            accy = __fadd_rn(accy, __fmul_rn(f[i].y, cw));
        }

        optr[l] = make_float2(accx, accy);

        off += (l == 0) ? 32768 : (l == 1) ? 262144 : 524288;
    }
}

extern "C" void kernel_launch(void* const* d_in, const int* in_sizes, int n_in,
                              void* d_out, int out_size) {
    const int n = in_sizes[0] / 4;          // number of points (262144)
    // block = 256 threads = 8 warps = 2 point-groups x 4 encodings
    dim3 block(256);
    dim3 grid(n / 64);
    energy4d_kernel<<<grid, block>>>(
        (const float4*)d_in[0], (const float4*)d_in[1],
        (const float2*)d_in[2], (const float2*)d_in[3],
        (const float2*)d_in[4], (const float2*)d_in[5],
        (float2*)d_out);
}

// round 5
// speedup vs baseline: 1.1652x; 1.1652x over previous
#include <cuda_runtime.h>
#include <stdint.h>

// Energy4D: 4x multi-resolution hash-grid encodings (instant-NGP style).
// L=16 levels, F=2 feats, HMAP=2^19, BASE=32, GROWTH=2 -> res_l = 32<<l.
// Level sizes: l0 dense 32768, l1 dense 262144, l>=2 hashed 524288 each.
//
// R4 -> R5: split into 4 sequential kernels of 4 levels each so the hot
// table slices (<=64 MB per group) stay L2-resident (L2 = 126 MB). Fine-level
// gathers then hit L2 instead of HBM: DRAM traffic ~2.1 GB -> ~0.4 GB.
//
// Numerics must match XLA's lowering bit-for-bit because pos = u*(res-1)
// amplifies ulp-level differences in u by up to 2^20.
//  - XLA algebraic simplifier: x / const -> x * rn(1/const)
//  - w = rn(u*resm1) - (float)p0_clipped   (plain sub, no fma)
// All math via __f*_rn intrinsics so --use_fast_math can't contract/approx.

constexpr unsigned HMASK = (1u << 19) - 1u;
constexpr unsigned P1 = 2654435761u;
constexpr unsigned P2 = 805459861u;

__device__ __host__ constexpr int level_offset(int l) {
    return (l == 0) ? 0 : (l == 1) ? 32768 : 294912 + (l - 2) * 524288;
}

__device__ __forceinline__ float clip01(float v) {
    return fminf(fmaxf(v, 0.0f), 1.0f);
}

template <int L0>
__global__ __launch_bounds__(256) void energy4d_group_kernel(
    const float4* __restrict__ coords,
    const float4* __restrict__ refc,
    const float2* __restrict__ t0,
    const float2* __restrict__ t1,
    const float2* __restrict__ t2,
    const float2* __restrict__ t3,
    float2* __restrict__ out)   // out as float2: elem = pt*64 + e*16 + l
{
    const int warp = threadIdx.x >> 5;
    const int lane = threadIdx.x & 31;
    const int e    = warp & 3;                               // encoding id
    const int pt   = (blockIdx.x * 2 + (warp >> 2)) * 32 + lane;

    const float4 c = coords[pt];
    const float4 r = refc[pt];

    // Compile-time correctly-rounded reciprocals (== XLA's folded 1/const).
    const float R180   = 1.0f / 180.0f;
    const float R360   = 1.0f / 360.0f;
    const float R20000 = 1.0f / 20000.0f;

    float nx = clip01(__fmul_rn(__fadd_rn(__fsub_rn(c.x, r.x), 90.0f),    R180));
    float ny = clip01(__fmul_rn(__fadd_rn(__fsub_rn(c.y, r.y), 180.0f),   R360));
    float nz = clip01(__fmul_rn(__fadd_rn(__fsub_rn(c.z, r.z), 11000.0f), R20000));
    float nt = clip01(__fsub_rn(c.w, r.w));
    float tsn = __fmul_rn(__fsub_rn(__fmul_rn(nt, 2.0f), 1.0f), 0.9f);

    float ux = clip01(__fmul_rn(__fadd_rn(nx,  1.0f), 0.5f));
    float uy = clip01(__fmul_rn(__fadd_rn(ny,  1.0f), 0.5f));
    float uz = clip01(__fmul_rn(__fadd_rn(nz,  1.0f), 0.5f));
    float ut = clip01(__fmul_rn(__fadd_rn(tsn, 1.0f), 0.5f));

    // encoding dim selection: e0=(x,y,z) e1=(x,y,t) e2=(y,z,t) e3=(x,z,t)
    const float ua = (e == 2) ? uy : ux;
    const float ub = (e <= 1) ? uy : uz;
    const float uc = (e == 0) ? uz : ut;
    const float2* __restrict__ tbl =
        (e == 0) ? t0 : (e == 1) ? t1 : (e == 2) ? t2 : t3;

    // 4 consecutive float2 per thread -> one aligned 32B sector store
    float2* optr = out + (size_t)pt * 64 + (size_t)e * 16 + L0;

    #pragma unroll
    for (int j = 0; j < 4; ++j) {
        constexpr int dummy = 0; (void)dummy;
        const int   l     = L0 + j;
        const int   res   = 32 << l;
        const float resm1 = (float)(res - 1);
        const int   off   = level_offset(L0 + j);

        float pa = __fmul_rn(ua, resm1);
        float pb = __fmul_rn(ub, resm1);
        float pc = __fmul_rn(uc, resm1);
        int a0 = min(max((int)floorf(pa), 0), res - 2);
        int b0 = min(max((int)floorf(pb), 0), res - 2);
        int c0 = min(max((int)floorf(pc), 0), res - 2);
        float wa = __fsub_rn(pa, (float)a0);
        float wb = __fsub_rn(pb, (float)b0);
        float wc = __fsub_rn(pc, (float)c0);

        int idx[8];
        if (l >= 2) {
            // hashed: h = a*1 ^ b*P1 ^ c*P2 (uint32 wrap), idx = (h & HMASK) + off
            unsigned ha0 = (unsigned)a0,      ha1 = ha0 + 1u;
            unsigned hb0 = (unsigned)b0 * P1, hb1 = hb0 + P1;
            unsigned hc0 = (unsigned)c0 * P2, hc1 = hc0 + P2;
            idx[0] = (int)((ha0 ^ hb0 ^ hc0) & HMASK) + off;
            idx[1] = (int)((ha1 ^ hb0 ^ hc0) & HMASK) + off;
            idx[2] = (int)((ha0 ^ hb1 ^ hc0) & HMASK) + off;
            idx[3] = (int)((ha1 ^ hb1 ^ hc0) & HMASK) + off;
            idx[4] = (int)((ha0 ^ hb0 ^ hc1) & HMASK) + off;
            idx[5] = (int)((ha1 ^ hb0 ^ hc1) & HMASK) + off;
            idx[6] = (int)((ha0 ^ hb1 ^ hc1) & HMASK) + off;
            idx[7] = (int)((ha1 ^ hb1 ^ hc1) & HMASK) + off;
        } else {
            // dense: idx = a + res*(b + res*c) + off
            const int rr = res * res;
            int base = a0 + res * (b0 + res * c0) + off;
            idx[0] = base;
            idx[1] = base + 1;
            idx[2] = base + res;
            idx[3] = base + res + 1;
            idx[4] = base + rr;
            idx[5] = base + rr + 1;
            idx[6] = base + rr + res;
            idx[7] = base + rr + res + 1;
        }

        float2 f[8];
        #pragma unroll
        for (int i = 0; i < 8; ++i) f[i] = __ldg(&tbl[idx[i]]);

        const float oma = __fsub_rn(1.0f, wa);
        const float omb = __fsub_rn(1.0f, wb);
        const float omc = __fsub_rn(1.0f, wc);
        float accx = 0.0f, accy = 0.0f;
        #pragma unroll
        for (int i = 0; i < 8; ++i) {
            float cwa = (i & 1) ? wa : oma;
            float cwb = (i & 2) ? wb : omb;
            float cwc = (i & 4) ? wc : omc;
            float cw  = __fmul_rn(__fmul_rn(cwa, cwb), cwc);
            accx = __fadd_rn(accx, __fmul_rn(f[i].x, cw));
            accy = __fadd_rn(accy, __fmul_rn(f[i].y, cw));
        }

        optr[j] = make_float2(accx, accy);
    }
}

extern "C" void kernel_launch(void* const* d_in, const int* in_sizes, int n_in,
                              void* d_out, int out_size) {
    const int n = in_sizes[0] / 4;          // number of points (262144)
    dim3 block(256);                        // 8 warps = 2 point-groups x 4 encodings
    dim3 grid(n / 64);
    const float4* coords = (const float4*)d_in[0];
    const float4* refc   = (const float4*)d_in[1];
    const float2* t0 = (const float2*)d_in[2];
    const float2* t1 = (const float2*)d_in[3];
    const float2* t2 = (const float2*)d_in[4];
    const float2* t3 = (const float2*)d_in[5];
    float2* out = (float2*)d_out;

    energy4d_group_kernel<0><<<grid, block>>>(coords, refc, t0, t1, t2, t3, out);
    energy4d_group_kernel<4><<<grid, block>>>(coords, refc, t0, t1, t2, t3, out);
    energy4d_group_kernel<8><<<grid, block>>>(coords, refc, t0, t1, t2, t3, out);
    energy4d_group_kernel<12><<<grid, block>>>(coords, refc, t0, t1, t2, t3, out);
}